// round 2
// baseline (speedup 1.0000x reference)
#include <cuda_runtime.h>
#include <math.h>

#define SS 4096
#define BB 128
#define HH 128
#define NCH 32
#define ROWS_PER_CHUNK (SS/NCH)   // 128

// scratch (no allocation allowed)
__device__ float g_q[BB*HH];
__device__ float g_pt[BB];
__device__ float g_Mp[NCH*BB];
__device__ float g_Lp[NCH*BB];
__device__ float g_out_scr[BB*HH];
__device__ float g_w_scr[SS*BB];

// ---------------------------------------------------------------------------
// Kernel A: q = d @ W_a ; p_t = S * sigmoid(tanh(d @ W_p) @ v_p)
// grid: BB blocks, HH threads
// ---------------------------------------------------------------------------
__global__ void prep_kernel(const float* __restrict__ d,
                            const float* __restrict__ Wa,
                            const float* __restrict__ Wp,
                            const float* __restrict__ vp) {
    int b = blockIdx.x, h = threadIdx.x;
    __shared__ float dsh[HH];
    dsh[h] = d[b*HH + h];
    __syncthreads();
    float qa = 0.f, qp = 0.f;
    #pragma unroll 8
    for (int k = 0; k < HH; k++) {
        float dv = dsh[k];
        qa += dv * Wa[k*HH + h];   // coalesced across h
        qp += dv * Wp[k*HH + h];
    }
    g_q[b*HH + h] = qa;
    __shared__ float red[HH];
    red[h] = tanhf(qp) * vp[h];
    __syncthreads();
    for (int off = HH/2; off > 0; off >>= 1) {
        if (h < off) red[h] += red[h+off];
        __syncthreads();
    }
    if (h == 0) {
        float z = red[0];
        g_pt[b] = (float)SS / (1.f + expf(-z));   // S * sigmoid(z)
    }
}

// ---------------------------------------------------------------------------
// Kernel B (dominant, DRAM-bound): per-(chunk,b) online softmax partials.
// grid: (NCH, BB), 256 threads (8 warps). Each warp: 16 rows, one row =
// 128 floats read as one float4 per lane (512B coalesced), dot with q.
// ---------------------------------------------------------------------------
__global__ void partials_kernel(const float* __restrict__ e) {
    int chunk = blockIdx.x, b = blockIdx.y;
    int warp = threadIdx.x >> 5, lane = threadIdx.x & 31;
    __shared__ float qsh[HH];
    if (threadIdx.x < HH) qsh[threadIdx.x] = g_q[b*HH + threadIdx.x];
    __syncthreads();
    float4 qv = reinterpret_cast<float4*>(qsh)[lane];

    float m = -INFINITY, l = 0.f;
    int r0 = chunk*ROWS_PER_CHUNK + warp*16;
    const float* ebase = e + ((size_t)r0*BB + b)*HH + lane*4;
    const size_t row_stride = (size_t)BB*HH;

    #pragma unroll
    for (int j = 0; j < 16; j += 2) {
        const float* p0 = ebase + (size_t)j*row_stride;
        const float* p1 = p0 + row_stride;
        float4 e0 = *reinterpret_cast<const float4*>(p0);
        float4 e1 = *reinterpret_cast<const float4*>(p1);
        float s0 = e0.x*qv.x + e0.y*qv.y + e0.z*qv.z + e0.w*qv.w;
        float s1 = e1.x*qv.x + e1.y*qv.y + e1.z*qv.z + e1.w*qv.w;
        #pragma unroll
        for (int off = 16; off; off >>= 1) {
            s0 += __shfl_xor_sync(0xffffffffu, s0, off);
            s1 += __shfl_xor_sync(0xffffffffu, s1, off);
        }
        float nm = fmaxf(m, fmaxf(s0, s1));
        l = l*expf(m - nm) + expf(s0 - nm) + expf(s1 - nm);
        m = nm;
    }
    __shared__ float sm[8], sl[8];
    if (lane == 0) { sm[warp] = m; sl[warp] = l; }
    __syncthreads();
    if (threadIdx.x == 0) {
        float M = -INFINITY;
        #pragma unroll
        for (int c = 0; c < 8; c++) M = fmaxf(M, sm[c]);
        float L = 0.f;
        #pragma unroll
        for (int c = 0; c < 8; c++) L += sl[c]*expf(sm[c]-M);
        g_Mp[chunk*BB + b] = M;
        g_Lp[chunk*BB + b] = L;
    }
}

// ---------------------------------------------------------------------------
// Zero the w output region (coalesced float4 stores); finalize then writes
// only the <=5 nonzero window entries per column.
// ---------------------------------------------------------------------------
__global__ void zero_w_kernel(float4* __restrict__ w) {
    int i = blockIdx.x*blockDim.x + threadIdx.x;
    w[i] = make_float4(0.f, 0.f, 0.f, 0.f);
}

// ---------------------------------------------------------------------------
// Kernel D: per-b — reduce chunk partials, recompute <=5 window scores,
// w = softmax * gauss, context, concat, tanh(x @ W_c).
// grid: BB blocks, HH threads
// ---------------------------------------------------------------------------
__global__ void finalize_kernel(const float* __restrict__ e,
                                const float* __restrict__ d,
                                const float* __restrict__ Wc,
                                float* __restrict__ out,
                                float* __restrict__ wout) {
    int b = blockIdx.x, h = threadIdx.x;
    int lane = h & 31, warp = h >> 5;
    __shared__ float qsh[HH];
    __shared__ float x[2*HH];
    __shared__ float wred[4];
    __shared__ float wvals[5];
    __shared__ float ML[2];
    qsh[h] = g_q[b*HH + h];
    if (h == 0) {
        float M = -INFINITY;
        for (int c = 0; c < NCH; c++) M = fmaxf(M, g_Mp[c*BB + b]);
        float L = 0.f;
        for (int c = 0; c < NCH; c++) L += g_Lp[c*BB + b]*expf(g_Mp[c*BB + b]-M);
        ML[0] = M; ML[1] = L;
    }
    __syncthreads();

    float pt = g_pt[b];
    int sf = (int)floorf(pt);
    int cs[5]; int cnt = 0;
    #pragma unroll
    for (int ds = -2; ds <= 2; ds++) {
        int s = sf + ds;
        if (s < 0 || s >= SS) continue;
        float diff = pt - (float)s;
        if (fabsf(diff) <= 2.0f) cs[cnt++] = s;   // exact reference mask
    }

    for (int i = 0; i < cnt; i++) {               // cnt uniform across block
        int s = cs[i];
        float prod = e[((size_t)s*BB + b)*HH + h] * qsh[h];
        #pragma unroll
        for (int off = 16; off; off >>= 1)
            prod += __shfl_xor_sync(0xffffffffu, prod, off);
        if (lane == 0) wred[warp] = prod;
        __syncthreads();
        if (h == 0) {
            float score = wred[0]+wred[1]+wred[2]+wred[3];
            float diff = pt - (float)s;
            float a = expf(score - ML[0]) / ML[1];
            wvals[i] = a * expf(-diff*diff*0.5f);  // sigma=1 -> /2
        }
        __syncthreads();
    }

    if (h < cnt) wout[(size_t)cs[h]*BB + b] = wvals[h];

    float ctx = 0.f;
    for (int i = 0; i < cnt; i++)
        ctx += e[((size_t)cs[i]*BB + b)*HH + h] * wvals[i];
    x[h]      = ctx;
    x[HH + h] = d[b*HH + h];
    __syncthreads();

    float acc = 0.f;
    #pragma unroll 8
    for (int k = 0; k < 2*HH; k++)
        acc += x[k] * Wc[k*HH + h];               // coalesced across h
    out[b*HH + h] = tanhf(acc);
}

// ---------------------------------------------------------------------------
extern "C" void kernel_launch(void* const* d_in, const int* in_sizes, int n_in,
                              void* d_out, int out_size) {
    const float* e  = (const float*)d_in[0];
    const float* d  = (const float*)d_in[1];
    const float* Wa = (const float*)d_in[2];
    const float* Wp = (const float*)d_in[3];
    const float* vp = (const float*)d_in[4];
    const float* Wc = (const float*)d_in[5];

    float* base = (float*)d_out;
    float* out_ptr;
    float* w_ptr;
    if (out_size >= BB*HH + SS*BB) {          // concatenated (output, w)
        out_ptr = base;
        w_ptr   = base + BB*HH;
    } else if (out_size == SS*BB) {           // only w expected
        cudaGetSymbolAddress((void**)&out_ptr, g_out_scr);
        w_ptr = base;
    } else {                                  // only output expected
        out_ptr = base;
        cudaGetSymbolAddress((void**)&w_ptr, g_w_scr);
    }

    prep_kernel<<<BB, HH>>>(d, Wa, Wp, vp);
    zero_w_kernel<<<(SS*BB/4)/256, 256>>>((float4*)w_ptr);
    partials_kernel<<<dim3(NCH, BB), 256>>>(e);
    finalize_kernel<<<BB, HH>>>(e, d, Wc, out_ptr, w_ptr);
}

// round 6
// speedup vs baseline: 1.3087x; 1.3087x over previous
#include <cuda_runtime.h>
#include <math.h>

#define SS 4096
#define BB 128
#define HH 128
#define NCH 32
#define ROWS_PER_CHUNK (SS/NCH)   // 128

// scratch (no allocation allowed)
__device__ float g_q[BB*HH];
__device__ float g_pt[BB];
__device__ float g_Mp[NCH*BB];
__device__ float g_Lp[NCH*BB];
__device__ float g_out_scr[BB*HH];
__device__ float g_w_scr[SS*BB];

// ---------------------------------------------------------------------------
// Kernel A: q = d @ W_a ; p_t = S * sigmoid(tanh(d @ W_p) @ v_p)
// grid: BB blocks, 256 threads: lower half computes qa, upper half qp.
// ---------------------------------------------------------------------------
__global__ void prep_kernel(const float* __restrict__ d,
                            const float* __restrict__ Wa,
                            const float* __restrict__ Wp,
                            const float* __restrict__ vp) {
    int b = blockIdx.x, t = threadIdx.x;
    int h = t & 127;
    __shared__ float dsh[HH];
    __shared__ float red[HH];
    if (t < HH) dsh[t] = d[b*HH + t];
    __syncthreads();

    const float* W = (t < HH) ? Wa : Wp;
    float acc = 0.f;
    #pragma unroll 16
    for (int k = 0; k < HH; k++)
        acc += dsh[k] * W[k*HH + h];          // coalesced across h

    if (t < HH) {
        g_q[b*HH + t] = acc;
    } else {
        red[h] = tanhf(acc) * vp[h];
    }
    __syncthreads();
    // tree reduce red[0..127] (guarded, full-block syncs)
    for (int off = HH/2; off > 0; off >>= 1) {
        if (t < off) red[t] += red[t+off];
        __syncthreads();
    }
    if (t == 0) {
        float z = red[0];
        g_pt[b] = (float)SS / (1.f + expf(-z));
    }
}

// ---------------------------------------------------------------------------
// Kernel B (dominant, DRAM-bound): per-(chunk,b) softmax partials.
// grid: (NCH, BB), 256 threads (8 warps). Warp handles 16 rows; raw scores
// computed first (deep load batching), then interleaved butterflies, then a
// single max + 16 independent exps. No loop-carried softmax chain.
// ---------------------------------------------------------------------------
__global__ void partials_kernel(const float* __restrict__ e) {
    int chunk = blockIdx.x, b = blockIdx.y;
    int warp = threadIdx.x >> 5, lane = threadIdx.x & 31;
    __shared__ float qsh[HH];
    if (threadIdx.x < HH) qsh[threadIdx.x] = g_q[b*HH + threadIdx.x];
    __syncthreads();
    float4 qv = reinterpret_cast<float4*>(qsh)[lane];

    int r0 = chunk*ROWS_PER_CHUNK + warp*16;
    const float* ebase = e + ((size_t)r0*BB + b)*HH + lane*4;
    const size_t rs = (size_t)BB*HH;

    float s[16];
    #pragma unroll
    for (int t = 0; t < 2; t++) {
        float4 ev[8];
        #pragma unroll
        for (int j = 0; j < 8; j++)
            ev[j] = *reinterpret_cast<const float4*>(ebase + (size_t)(t*8+j)*rs);
        #pragma unroll
        for (int j = 0; j < 8; j++)
            s[t*8+j] = ev[j].x*qv.x + ev[j].y*qv.y + ev[j].z*qv.z + ev[j].w*qv.w;
    }
    // 16 interleaved butterfly chains (latency overlapped)
    #pragma unroll
    for (int off = 16; off; off >>= 1) {
        #pragma unroll
        for (int j = 0; j < 16; j++)
            s[j] += __shfl_xor_sync(0xffffffffu, s[j], off);
    }
    float m = s[0];
    #pragma unroll
    for (int j = 1; j < 16; j++) m = fmaxf(m, s[j]);
    float l = 0.f;
    #pragma unroll
    for (int j = 0; j < 16; j++) l += __expf(s[j] - m);

    __shared__ float sm[8], sl[8];
    if (lane == 0) { sm[warp] = m; sl[warp] = l; }
    __syncthreads();
    if (threadIdx.x == 0) {
        float M = sm[0];
        #pragma unroll
        for (int c = 1; c < 8; c++) M = fmaxf(M, sm[c]);
        float L = 0.f;
        #pragma unroll
        for (int c = 0; c < 8; c++) L += sl[c]*__expf(sm[c]-M);
        g_Mp[chunk*BB + b] = M;
        g_Lp[chunk*BB + b] = L;
    }
}

// ---------------------------------------------------------------------------
__global__ void zero_w_kernel(float4* __restrict__ w) {
    int i = blockIdx.x*blockDim.x + threadIdx.x;
    w[i] = make_float4(0.f, 0.f, 0.f, 0.f);
}

// ---------------------------------------------------------------------------
// Kernel D: per-b. 256 threads. Warp-parallel chunk reduction, window rows
// staged once in shared, warp-per-row scores, k-split output GEMM.
// ---------------------------------------------------------------------------
__global__ void finalize_kernel(const float* __restrict__ e,
                                const float* __restrict__ d,
                                const float* __restrict__ Wc,
                                float* __restrict__ out,
                                float* __restrict__ wout) {
    int b = blockIdx.x, t = threadIdx.x;
    int lane = t & 31, warp = t >> 5;
    __shared__ float qsh[HH];
    __shared__ float esh[5][HH];
    __shared__ float x[2*HH];
    __shared__ float pacc[2*HH];
    __shared__ float scr[5];
    __shared__ float wvals[5];
    __shared__ float ML[2];

    if (t < HH) {
        qsh[t]    = g_q[b*HH + t];
        x[HH + t] = d[b*HH + t];
    }

    // warp 0: parallel chunk reduction (lane = chunk index)
    if (warp == 0) {
        float m = g_Mp[lane*BB + b];
        float l = g_Lp[lane*BB + b];
        float M = m;
        #pragma unroll
        for (int off = 16; off; off >>= 1)
            M = fmaxf(M, __shfl_xor_sync(0xffffffffu, M, off));
        float lc = l*__expf(m - M);
        #pragma unroll
        for (int off = 16; off; off >>= 1)
            lc += __shfl_xor_sync(0xffffffffu, lc, off);
        if (lane == 0) { ML[0] = M; ML[1] = lc; }
    }

    // window candidates (uniform per block)
    float pt = g_pt[b];
    int sf = (int)floorf(pt);
    int cs[5]; int cnt = 0;
    #pragma unroll
    for (int ds = -2; ds <= 2; ds++) {
        int s = sf + ds;
        if (s < 0 || s >= SS) continue;
        float diff = pt - (float)s;
        if (fabsf(diff) <= 2.0f) cs[cnt++] = s;
    }

    // stage all window rows into shared (parallel loads)
    for (int idx = t; idx < cnt*HH; idx += 256) {
        int i = idx >> 7, h = idx & 127;
        esh[i][h] = e[((size_t)cs[i]*BB + b)*HH + h];
    }
    __syncthreads();

    // warp i computes score of window row i (i < cnt <= 5)
    if (warp < cnt) {
        float v = 0.f;
        #pragma unroll
        for (int j = 0; j < 4; j++)
            v += esh[warp][lane + 32*j] * qsh[lane + 32*j];
        #pragma unroll
        for (int off = 16; off; off >>= 1)
            v += __shfl_xor_sync(0xffffffffu, v, off);
        if (lane == 0) scr[warp] = v;
    }
    __syncthreads();

    if (t < cnt) {
        float diff = pt - (float)cs[t];
        float a = expf(scr[t] - ML[0]) / ML[1];
        float v = a * expf(-diff*diff*0.5f);
        wvals[t] = v;
        wout[(size_t)cs[t]*BB + b] = v;
    }
    __syncthreads();

    if (t < HH) {
        float ctx = 0.f;
        for (int i = 0; i < cnt; i++)
            ctx += esh[i][t] * wvals[i];
        x[t] = ctx;
    }
    __syncthreads();

    // output GEMM, k split across two thread halves
    {
        int h = t & 127, part = t >> 7;
        const float* Wcp = Wc + (size_t)part*HH*HH;
        float acc = 0.f;
        #pragma unroll 16
        for (int k = 0; k < HH; k++)
            acc += x[part*HH + k] * Wcp[k*HH + h];
        pacc[t] = acc;
    }
    __syncthreads();
    if (t < HH)
        out[b*HH + t] = tanhf(pacc[t] + pacc[t + HH]);
}

// ---------------------------------------------------------------------------
extern "C" void kernel_launch(void* const* d_in, const int* in_sizes, int n_in,
                              void* d_out, int out_size) {
    const float* e  = (const float*)d_in[0];
    const float* d  = (const float*)d_in[1];
    const float* Wa = (const float*)d_in[2];
    const float* Wp = (const float*)d_in[3];
    const float* vp = (const float*)d_in[4];
    const float* Wc = (const float*)d_in[5];

    float* base = (float*)d_out;
    float* out_ptr;
    float* w_ptr;
    if (out_size >= BB*HH + SS*BB) {
        out_ptr = base;
        w_ptr   = base + BB*HH;
    } else if (out_size == SS*BB) {
        cudaGetSymbolAddress((void**)&out_ptr, g_out_scr);
        w_ptr = base;
    } else {
        out_ptr = base;
        cudaGetSymbolAddress((void**)&w_ptr, g_w_scr);
    }

    zero_w_kernel<<<(SS*BB/4)/256, 256>>>((float4*)w_ptr);
    prep_kernel<<<BB, 256>>>(d, Wa, Wp, vp);
    partials_kernel<<<dim3(NCH, BB), 256>>>(e);
    finalize_kernel<<<BB, 256>>>(e, d, Wc, out_ptr, w_ptr);
}

// round 8
// speedup vs baseline: 1.3502x; 1.0317x over previous
#include <cuda_runtime.h>
#include <math.h>

#define SS 4096
#define BB 128
#define HH 128
#define NCH 32
#define ROWS_PER_CHUNK (SS/NCH)   // 128
#define ZERO_BLOCKS 512           // SS*BB/4 float4 / 256 threads

// scratch (no allocation allowed)
__device__ float g_q[BB*HH];
__device__ float g_pt[BB];
__device__ float g_Mp[NCH*BB];
__device__ float g_Lp[NCH*BB];
__device__ int   g_cnt[BB];
__device__ float g_out_scr[BB*HH];
__device__ float g_w_scr[SS*BB];

// ---------------------------------------------------------------------------
// Kernel 1 (setup): blocks [0,512) zero w; blocks [512,640) do prep for one b
// (q = d@W_a, p_t = S*sigmoid(tanh(d@W_p)@v_p)) and reset g_cnt[b].
// ---------------------------------------------------------------------------
__global__ void setup_kernel(const float* __restrict__ d,
                             const float* __restrict__ Wa,
                             const float* __restrict__ Wp,
                             const float* __restrict__ vp,
                             float4* __restrict__ wzero) {
    int blk = blockIdx.x, t = threadIdx.x;
    if (blk < ZERO_BLOCKS) {
        wzero[blk*256 + t] = make_float4(0.f, 0.f, 0.f, 0.f);
        return;
    }
    int b = blk - ZERO_BLOCKS;
    if (t == 0) g_cnt[b] = 0;

    int h = t & 127;
    __shared__ float dsh[HH];
    __shared__ float red[HH];
    if (t < HH) dsh[t] = d[b*HH + t];
    __syncthreads();

    const float* W = (t < HH) ? Wa : Wp;
    float acc = 0.f;
    #pragma unroll 16
    for (int k = 0; k < HH; k++)
        acc += dsh[k] * W[k*HH + h];          // coalesced across h

    if (t < HH) {
        g_q[b*HH + t] = acc;
    } else {
        red[h] = tanhf(acc) * vp[h];
    }
    __syncthreads();
    for (int off = HH/2; off > 0; off >>= 1) {
        if (t < off) red[t] += red[t+off];
        __syncthreads();
    }
    if (t == 0) {
        float z = red[0];
        g_pt[b] = (float)SS / (1.f + expf(-z));
    }
}

// ---------------------------------------------------------------------------
// Kernel 2 (fused, DRAM-bound): per-(chunk,b) softmax partials; the LAST
// block to finish for a given b (atomic counter) performs the entire
// finalize for that b in-kernel, overlapped with remaining streaming blocks.
// grid: (NCH, BB), 256 threads (8 warps).
// ---------------------------------------------------------------------------
__global__ void __launch_bounds__(256)
fused_kernel(const float* __restrict__ e,
             const float* __restrict__ d,
             const float* __restrict__ Wc,
             float* __restrict__ out,
             float* __restrict__ wout) {
    int chunk = blockIdx.x, b = blockIdx.y;
    int warp = threadIdx.x >> 5, lane = threadIdx.x & 31;
    int t = threadIdx.x;

    __shared__ float qsh[HH];
    __shared__ float sm[8], sl[8];
    __shared__ int islast;

    if (t < HH) qsh[t] = g_q[b*HH + t];
    __syncthreads();
    float4 qv = reinterpret_cast<float4*>(qsh)[lane];

    int r0 = chunk*ROWS_PER_CHUNK + warp*16;
    const float* ebase = e + ((size_t)r0*BB + b)*HH + lane*4;
    const size_t rs = (size_t)BB*HH;

    float s[16];
    #pragma unroll
    for (int tt = 0; tt < 2; tt++) {
        float4 ev[8];
        #pragma unroll
        for (int j = 0; j < 8; j++)
            ev[j] = *reinterpret_cast<const float4*>(ebase + (size_t)(tt*8+j)*rs);
        #pragma unroll
        for (int j = 0; j < 8; j++)
            s[tt*8+j] = ev[j].x*qv.x + ev[j].y*qv.y + ev[j].z*qv.z + ev[j].w*qv.w;
    }
    #pragma unroll
    for (int off = 16; off; off >>= 1) {
        #pragma unroll
        for (int j = 0; j < 16; j++)
            s[j] += __shfl_xor_sync(0xffffffffu, s[j], off);
    }
    float m = s[0];
    #pragma unroll
    for (int j = 1; j < 16; j++) m = fmaxf(m, s[j]);
    float l = 0.f;
    #pragma unroll
    for (int j = 0; j < 16; j++) l += __expf(s[j] - m);

    if (lane == 0) { sm[warp] = m; sl[warp] = l; }
    __syncthreads();
    if (t == 0) {
        float M = sm[0];
        #pragma unroll
        for (int c = 1; c < 8; c++) M = fmaxf(M, sm[c]);
        float L = 0.f;
        #pragma unroll
        for (int c = 0; c < 8; c++) L += sl[c]*__expf(sm[c]-M);
        g_Mp[chunk*BB + b] = M;
        g_Lp[chunk*BB + b] = L;
        __threadfence();
        int old = atomicAdd(&g_cnt[b], 1);
        islast = (old == NCH-1);
    }
    __syncthreads();
    if (!islast) return;

    // ===================== finalize for this b (last block) =================
    __shared__ float esh[5][HH];
    __shared__ float x[2*HH];
    __shared__ float pacc[2*HH];
    __shared__ float scr[5];
    __shared__ float wvals[5];
    __shared__ float ML[2];

    if (t < HH) x[HH + t] = d[b*HH + t];

    // warp 0: parallel chunk reduction (lane = chunk index)
    if (warp == 0) {
        float mm = ((const volatile float*)g_Mp)[lane*BB + b];
        float ll = ((const volatile float*)g_Lp)[lane*BB + b];
        float M = mm;
        #pragma unroll
        for (int off = 16; off; off >>= 1)
            M = fmaxf(M, __shfl_xor_sync(0xffffffffu, M, off));
        float lc = ll*__expf(mm - M);
        #pragma unroll
        for (int off = 16; off; off >>= 1)
            lc += __shfl_xor_sync(0xffffffffu, lc, off);
        if (lane == 0) { ML[0] = M; ML[1] = lc; }
    }

    // window candidates (uniform per block)
    float pt = g_pt[b];
    int sf = (int)floorf(pt);
    int cs[5]; int cnt = 0;
    #pragma unroll
    for (int ds = -2; ds <= 2; ds++) {
        int sidx = sf + ds;
        if (sidx < 0 || sidx >= SS) continue;
        float diff = pt - (float)sidx;
        if (fabsf(diff) <= 2.0f) cs[cnt++] = sidx;
    }

    // stage window rows into shared (parallel loads)
    for (int idx = t; idx < cnt*HH; idx += 256) {
        int i = idx >> 7, h = idx & 127;
        esh[i][h] = e[((size_t)cs[i]*BB + b)*HH + h];
    }
    __syncthreads();

    // warp i computes score of window row i
    if (warp < cnt) {
        float v = 0.f;
        #pragma unroll
        for (int j = 0; j < 4; j++)
            v += esh[warp][lane + 32*j] * qsh[lane + 32*j];
        #pragma unroll
        for (int off = 16; off; off >>= 1)
            v += __shfl_xor_sync(0xffffffffu, v, off);
        if (lane == 0) scr[warp] = v;
    }
    __syncthreads();

    if (t < cnt) {
        float diff = pt - (float)cs[t];
        float a = expf(scr[t] - ML[0]) / ML[1];
        float v = a * expf(-diff*diff*0.5f);
        wvals[t] = v;
        wout[(size_t)cs[t]*BB + b] = v;
    }
    __syncthreads();

    if (t < HH) {
        float ctx = 0.f;
        for (int i = 0; i < cnt; i++)
            ctx += esh[i][t] * wvals[i];
        x[t] = ctx;
    }
    __syncthreads();

    // output GEMM, 2-way k-split
    {
        int h = t & 127, part = t >> 7;
        const float* Wcp = Wc + (size_t)part*HH*HH;
        float acc = 0.f;
        #pragma unroll 16
        for (int k = 0; k < HH; k++)
            acc += x[part*HH + k] * Wcp[k*HH + h];
        pacc[t] = acc;
    }
    __syncthreads();
    if (t < HH)
        out[b*HH + t] = tanhf(pacc[t] + pacc[t + HH]);
}

// ---------------------------------------------------------------------------
extern "C" void kernel_launch(void* const* d_in, const int* in_sizes, int n_in,
                              void* d_out, int out_size) {
    const float* e  = (const float*)d_in[0];
    const float* d  = (const float*)d_in[1];
    const float* Wa = (const float*)d_in[2];
    const float* Wp = (const float*)d_in[3];
    const float* vp = (const float*)d_in[4];
    const float* Wc = (const float*)d_in[5];

    float* base = (float*)d_out;
    float* out_ptr;
    float* w_ptr;
    if (out_size >= BB*HH + SS*BB) {
        out_ptr = base;
        w_ptr   = base + BB*HH;
    } else if (out_size == SS*BB) {
        cudaGetSymbolAddress((void**)&out_ptr, g_out_scr);
        w_ptr = base;
    } else {
        out_ptr = base;
        cudaGetSymbolAddress((void**)&w_ptr, g_w_scr);
    }

    setup_kernel<<<ZERO_BLOCKS + BB, 256>>>(d, Wa, Wp, vp, (float4*)w_ptr);
    fused_kernel<<<dim3(NCH, BB), 256>>>(e, d, Wc, out_ptr, w_ptr);
}

// round 13
// speedup vs baseline: 1.4239x; 1.0545x over previous
#include <cuda_runtime.h>
#include <math.h>

#define SS 4096
#define BB 128
#define HH 128
#define NCH 8
#define ROWS_PER_CHUNK (SS/NCH)   // 512 rows per block, 64 per warp

// scratch (no allocation allowed)
__device__ float g_Mp[NCH*BB];
__device__ float g_Lp[NCH*BB];
__device__ int   g_cnt[BB];       // zero-init at load; reset by last block
__device__ float g_out_scr[BB*HH];
__device__ float g_w_scr[SS*BB];

// array-halving combine: after this, lanes with (lane&off)==0 hold a's
// cross-half partial, lanes with bit set hold b's.
__device__ __forceinline__ float comb(float a, float b, int off, int lane) {
    float keep = (lane & off) ? b : a;
    float send = (lane & off) ? a : b;
    return keep + __shfl_xor_sync(0xffffffffu, send, off);
}

__global__ void __launch_bounds__(256)
fused_kernel(const float* __restrict__ e,
             const float* __restrict__ d,
             const float* __restrict__ Wa,
             const float* __restrict__ Wp,
             const float* __restrict__ vp,
             const float* __restrict__ Wc,
             float* __restrict__ out,
             float* __restrict__ wout) {
    int chunk = blockIdx.x, b = blockIdx.y;
    int t = threadIdx.x;
    int warp = t >> 5, lane = t & 31;

    __shared__ float dsh[HH];
    __shared__ float qsh[HH];
    __shared__ float pacc[2*HH];
    __shared__ float sm[8], sl[8];
    __shared__ float esh[5][HH];
    __shared__ float x[2*HH];
    __shared__ float scr[5];
    __shared__ float wvals[5];
    __shared__ float ML[3];
    __shared__ int islast;

    // ---- issue group-0 e loads FIRST (latency covers q GEMV) ----
    int R0 = chunk*ROWS_PER_CHUNK + warp*64;
    const float* ebase = e + ((size_t)R0*BB + b)*HH + lane*4;
    const size_t rstride = (size_t)BB*HH;
    float4 ev[8];
    #pragma unroll
    for (int j = 0; j < 8; j++)
        ev[j] = __ldcs(reinterpret_cast<const float4*>(ebase + (size_t)j*rstride));

    // ---- in-block q = d[b]@W_a (W_a is L2-resident across 1024 blocks) ----
    if (t < HH) dsh[t] = d[b*HH + t];
    __syncthreads();
    {
        int h = t & 127, half = t >> 7;
        float acc = 0.f;
        #pragma unroll 16
        for (int k = half*64; k < half*64 + 64; k++)
            acc += dsh[k] * Wa[k*HH + h];      // coalesced across h
        pacc[t] = acc;
    }
    __syncthreads();
    if (t < HH) qsh[t] = pacc[t] + pacc[t + HH];
    __syncthreads();
    float4 qv = reinterpret_cast<float4*>(qsh)[lane];

    // ---- zero this block's slice of w (ordered before finalize via fence+atomic) ----
    {
        int rbase = chunk*ROWS_PER_CHUNK;
        wout[(size_t)(rbase + t)*BB + b] = 0.f;
        wout[(size_t)(rbase + t + 256)*BB + b] = 0.f;
    }

    // ---- stream 8 groups of 8 rows; cheap halving reduction ----
    float rs[8];
    #pragma unroll
    for (int g = 0; g < 8; g++) {
        float s[8];
        #pragma unroll
        for (int j = 0; j < 8; j++)
            s[j] = ev[j].x*qv.x + ev[j].y*qv.y + ev[j].z*qv.z + ev[j].w*qv.w;
        if (g < 7) {
            const float* nb = ebase + (size_t)(g+1)*8*rstride;
            #pragma unroll
            for (int j = 0; j < 8; j++)
                ev[j] = __ldcs(reinterpret_cast<const float4*>(nb + (size_t)j*rstride));
        }
        float r0 = comb(s[0], s[1], 16, lane);
        float r1 = comb(s[2], s[3], 16, lane);
        float r2 = comb(s[4], s[5], 16, lane);
        float r3 = comb(s[6], s[7], 16, lane);
        float u0 = comb(r0, r1, 8, lane);
        float u1 = comb(r2, r3, 8, lane);
        float v0 = comb(u0, u1, 4, lane);
        v0 += __shfl_xor_sync(0xffffffffu, v0, 2);
        v0 += __shfl_xor_sync(0xffffffffu, v0, 1);
        rs[g] = v0;                 // one complete row-score per lane (x4 copies)
    }

    // warp (M, L) over its 64 rows
    float m = rs[0];
    #pragma unroll
    for (int g = 1; g < 8; g++) m = fmaxf(m, rs[g]);
    #pragma unroll
    for (int off = 16; off; off >>= 1)
        m = fmaxf(m, __shfl_xor_sync(0xffffffffu, m, off));
    float l = 0.f;
    #pragma unroll
    for (int g = 0; g < 8; g++) l += __expf(rs[g] - m);
    #pragma unroll
    for (int off = 16; off; off >>= 1)
        l += __shfl_xor_sync(0xffffffffu, l, off);
    l *= 0.25f;                      // each row counted exactly 4x

    if (lane == 0) { sm[warp] = m; sl[warp] = l; }
    __syncthreads();
    if (t == 0) {
        float M = sm[0];
        #pragma unroll
        for (int c = 1; c < 8; c++) M = fmaxf(M, sm[c]);
        float L = 0.f;
        #pragma unroll
        for (int c = 0; c < 8; c++) L += sl[c]*__expf(sm[c]-M);
        g_Mp[chunk*BB + b] = M;
        g_Lp[chunk*BB + b] = L;
        __threadfence();
        int old = atomicAdd(&g_cnt[b], 1);
        islast = (old == NCH-1);
        if (old == NCH-1) g_cnt[b] = 0;   // reset for next graph replay
    }
    __syncthreads();
    if (!islast) return;

    // ===================== finalize for this b (last block) =================
    __threadfence();

    // p_t = S * sigmoid(tanh(d@W_p)@v_p)  (only 128 blocks run this)
    {
        int h = t & 127, half = t >> 7;
        float acc = 0.f;
        #pragma unroll 16
        for (int k = half*64; k < half*64 + 64; k++)
            acc += dsh[k] * Wp[k*HH + h];
        pacc[t] = acc;
    }
    __syncthreads();
    if (t < HH) pacc[t] = tanhf(pacc[t] + pacc[t + HH]) * vp[t];
    __syncthreads();
    for (int off = HH/2; off > 0; off >>= 1) {
        if (t < off) pacc[t] += pacc[t+off];
        __syncthreads();
    }
    if (t == 0) {
        float z = pacc[0];
        ML[2] = (float)SS / (1.f + expf(-z));
    }

    // global (M, L) over 8 chunk partials (warp 0)
    if (warp == 0) {
        float mm = (lane < NCH) ? ((const volatile float*)g_Mp)[lane*BB + b] : -INFINITY;
        float ll = (lane < NCH) ? ((const volatile float*)g_Lp)[lane*BB + b] : 0.f;
        float M = mm;
        #pragma unroll
        for (int off = 16; off; off >>= 1)
            M = fmaxf(M, __shfl_xor_sync(0xffffffffu, M, off));
        float lc = ll*__expf(mm - M);
        #pragma unroll
        for (int off = 16; off; off >>= 1)
            lc += __shfl_xor_sync(0xffffffffu, lc, off);
        if (lane == 0) { ML[0] = M; ML[1] = lc; }
    }
    __syncthreads();

    // window candidates (uniform per block)
    float pt = ML[2];
    int sf = (int)floorf(pt);
    int cs[5]; int cnt = 0;
    #pragma unroll
    for (int ds = -2; ds <= 2; ds++) {
        int sidx = sf + ds;
        if (sidx < 0 || sidx >= SS) continue;
        float diff = pt - (float)sidx;
        if (fabsf(diff) <= 2.0f) cs[cnt++] = sidx;
    }

    // stage window rows into shared (parallel loads)
    for (int idx = t; idx < cnt*HH; idx += 256) {
        int i = idx >> 7, h = idx & 127;
        esh[i][h] = e[((size_t)cs[i]*BB + b)*HH + h];
    }
    if (t < HH) x[HH + t] = dsh[t];
    __syncthreads();

    // warp i: score of window row i
    if (warp < cnt) {
        float v = 0.f;
        #pragma unroll
        for (int j = 0; j < 4; j++)
            v += esh[warp][lane + 32*j] * qsh[lane + 32*j];
        #pragma unroll
        for (int off = 16; off; off >>= 1)
            v += __shfl_xor_sync(0xffffffffu, v, off);
        if (lane == 0) scr[warp] = v;
    }
    __syncthreads();

    if (t < cnt) {
        float diff = pt - (float)cs[t];
        float a = expf(scr[t] - ML[0]) / ML[1];
        float v = a * expf(-diff*diff*0.5f);
        wvals[t] = v;
        wout[(size_t)cs[t]*BB + b] = v;
    }
    __syncthreads();

    if (t < HH) {
        float ctx = 0.f;
        for (int i = 0; i < cnt; i++)
            ctx += esh[i][t] * wvals[i];
        x[t] = ctx;
    }
    __syncthreads();

    // output GEMM, 2-way k-split
    {
        int h = t & 127, part = t >> 7;
        const float* Wcp = Wc + (size_t)part*HH*HH;
        float acc = 0.f;
        #pragma unroll 16
        for (int k = 0; k < HH; k++)
            acc += x[part*HH + k] * Wcp[k*HH + h];
        pacc[t] = acc;
    }
    __syncthreads();
    if (t < HH)
        out[b*HH + t] = tanhf(pacc[t] + pacc[t + HH]);
}

// ---------------------------------------------------------------------------
extern "C" void kernel_launch(void* const* d_in, const int* in_sizes, int n_in,
                              void* d_out, int out_size) {
    const float* e  = (const float*)d_in[0];
    const float* d  = (const float*)d_in[1];
    const float* Wa = (const float*)d_in[2];
    const float* Wp = (const float*)d_in[3];
    const float* vp = (const float*)d_in[4];
    const float* Wc = (const float*)d_in[5];

    float* base = (float*)d_out;
    float* out_ptr;
    float* w_ptr;
    if (out_size >= BB*HH + SS*BB) {
        out_ptr = base;
        w_ptr   = base + BB*HH;
    } else if (out_size == SS*BB) {
        cudaGetSymbolAddress((void**)&out_ptr, g_out_scr);
        w_ptr = base;
    } else {
        out_ptr = base;
        cudaGetSymbolAddress((void**)&w_ptr, g_w_scr);
    }

    fused_kernel<<<dim3(NCH, BB), 256>>>(e, d, Wa, Wp, vp, Wc, out_ptr, w_ptr);
}